// round 2
// baseline (speedup 1.0000x reference)
#include <cuda_runtime.h>

// Problem constants (B=2, H=16, N=2048, D=64)
#define THREADS 256
#define TQ      16          // query rows per CTA
#define TK      256         // key tile rows
#define DH      64          // head dim
#define NSEQ    2048
#define LDK     (DH + 4)    // padded smem row stride (floats)
#define NEG_INF_F (-1000000000.0f)

// dynamic smem layout:
//   float S [TQ][NSEQ]   : score / prob tile        (131072 B)
//   float Ks[TK][LDK]    : K tile (reused for V)    ( 69632 B)
//   float Qs[TQ][LDK]    : Q tile, pre-scaled 1/8   (  4352 B)
//   int   mks[NSEQ]      : key-side mask            (  8192 B)
//   int   mqs[TQ]        : query-side mask          (    64 B)
#define SMEM_BYTES ((TQ*NSEQ + TK*LDK + TQ*LDK) * 4 + NSEQ * 4 + TQ * 4)

__global__ __launch_bounds__(THREADS, 1)
void attn_fused_kernel(const float* __restrict__ gq,
                       const float* __restrict__ gk,
                       const float* __restrict__ gv,
                       const int*   __restrict__ gmask,
                       float* __restrict__ gout,
                       float* __restrict__ gattn)
{
    extern __shared__ float sm[];
    float* S   = sm;                          // TQ * NSEQ
    float* Ks  = S  + TQ * NSEQ;              // TK * LDK
    float* Qs  = Ks + TK * LDK;               // TQ * LDK
    int*   mks = (int*)(Qs + TQ * LDK);       // NSEQ
    int*   mqs = mks + NSEQ;                  // TQ

    const int tid = threadIdx.x;
    const int bh  = blockIdx.y;               // 0..31 (b*16 + h)
    const int b   = bh >> 4;
    const int q0  = blockIdx.x * TQ;

    const float* qbase = gq + ((size_t)bh * NSEQ + q0) * DH;
    const float* kbase = gk + (size_t)bh * NSEQ * DH;
    const float* vbase = gv + (size_t)bh * NSEQ * DH;

    // ---- mask + Q tile load (Q pre-scaled by 1/TEMPERATURE = 0.125, exact) ----
    for (int i = tid; i < NSEQ; i += THREADS) mks[i] = gmask[b * NSEQ + i];
    if (tid < TQ) mqs[tid] = gmask[b * NSEQ + q0 + tid];
    {
        int r = tid >> 4;
        int d = (tid & 15) << 2;
        float4 qv = *(const float4*)(qbase + r * DH + d);
        qv.x *= 0.125f; qv.y *= 0.125f; qv.z *= 0.125f; qv.w *= 0.125f;
        *(float4*)&Qs[r * LDK + d] = qv;
    }

    // ---- S = (Q/8) K^T with symmetric mask -> NEG_INF ----
    const int r0 = (tid >> 6) << 2;   // 0,4,8,12
    const int c0 = (tid & 63) << 2;   // 0..252 step 4

    for (int kt = 0; kt < NSEQ; kt += TK) {
        __syncthreads();
        #pragma unroll
        for (int i = 0; i < (TK * DH / 4) / THREADS; i++) {   // 16 float4 each
            int idx = tid + i * THREADS;
            int row = idx >> 4;
            int d   = (idx & 15) << 2;
            *(float4*)&Ks[row * LDK + d] =
                *(const float4*)(kbase + (size_t)(kt + row) * DH + d);
        }
        __syncthreads();

        float acc[4][4] = {};
        #pragma unroll 4
        for (int d = 0; d < DH; d += 4) {
            float4 qa[4], kb[4];
            #pragma unroll
            for (int i = 0; i < 4; i++) qa[i] = *(const float4*)&Qs[(r0 + i) * LDK + d];
            #pragma unroll
            for (int j = 0; j < 4; j++) kb[j] = *(const float4*)&Ks[(c0 + j) * LDK + d];
            #pragma unroll
            for (int i = 0; i < 4; i++)
                #pragma unroll
                for (int j = 0; j < 4; j++)
                    acc[i][j] += qa[i].x * kb[j].x + qa[i].y * kb[j].y
                               + qa[i].z * kb[j].z + qa[i].w * kb[j].w;
        }

        int mk0 = mks[kt + c0 + 0], mk1 = mks[kt + c0 + 1];
        int mk2 = mks[kt + c0 + 2], mk3 = mks[kt + c0 + 3];
        #pragma unroll
        for (int i = 0; i < 4; i++) {
            int mq = mqs[r0 + i];
            float4 sv;
            sv.x = (mq | mk0) ? NEG_INF_F : acc[i][0];
            sv.y = (mq | mk1) ? NEG_INF_F : acc[i][1];
            sv.z = (mq | mk2) ? NEG_INF_F : acc[i][2];
            sv.w = (mq | mk3) ? NEG_INF_F : acc[i][3];
            *(float4*)&S[(size_t)(r0 + i) * NSEQ + kt + c0] = sv;
        }
    }

    __syncthreads();

    // ---- row softmax in smem; stream normalized probs to gattn ----
    const int warp = tid >> 5;
    const int lane = tid & 31;
    for (int r = warp; r < TQ; r += 8) {
        float* row = &S[(size_t)r * NSEQ];
        float m = NEG_INF_F;
        for (int i = lane; i < NSEQ; i += 32) m = fmaxf(m, row[i]);
        #pragma unroll
        for (int o = 16; o > 0; o >>= 1) m = fmaxf(m, __shfl_xor_sync(0xffffffffu, m, o));
        float l = 0.0f;
        for (int i = lane; i < NSEQ; i += 32) {
            float e = __expf(row[i] - m);   // masked row: all exp(0)=1 -> uniform 1/N (matches ref)
            row[i] = e;
            l += e;
        }
        #pragma unroll
        for (int o = 16; o > 0; o >>= 1) l += __shfl_xor_sync(0xffffffffu, l, o);
        float inv = 1.0f / l;
        float* arow = gattn + ((size_t)bh * NSEQ + q0 + r) * NSEQ;
        for (int i = lane; i < NSEQ; i += 32) {
            float p = row[i] * inv;
            row[i]  = p;        // keep prob in smem for PV
            arow[i] = p;        // coalesced attn write
        }
    }

    // ---- O = P V : per-thread 1q x 8d, k-range split across block halves ----
    const int half = tid >> 7;            // 0 or 1
    const int u    = tid & 127;
    const int rr   = u >> 3;              // 0..15
    const int cc   = (u & 7) << 3;        // 0,8,...,56
    float o[8] = {0,0,0,0,0,0,0,0};

    for (int kt = 0; kt < NSEQ; kt += TK) {
        __syncthreads();
        #pragma unroll
        for (int i = 0; i < (TK * DH / 4) / THREADS; i++) {   // V tile into Ks
            int idx = tid + i * THREADS;
            int row = idx >> 4;
            int d   = (idx & 15) << 2;
            *(float4*)&Ks[row * LDK + d] =
                *(const float4*)(vbase + (size_t)(kt + row) * DH + d);
        }
        __syncthreads();

        const int kbeg = half * (TK / 2);
        #pragma unroll 8
        for (int kk = 0; kk < TK / 2; kk += 4) {
            int krow = kbeg + kk;
            float4 p4 = *(const float4*)&S[(size_t)rr * NSEQ + kt + krow];
            #pragma unroll
            for (int t = 0; t < 4; t++) {
                float pt = (t == 0) ? p4.x : (t == 1) ? p4.y : (t == 2) ? p4.z : p4.w;
                const float* vrow = &Ks[(krow + t) * LDK + cc];
                float4 va = *(const float4*)vrow;
                float4 vb = *(const float4*)(vrow + 4);
                o[0] += pt * va.x; o[1] += pt * va.y; o[2] += pt * va.z; o[3] += pt * va.w;
                o[4] += pt * vb.x; o[5] += pt * vb.y; o[6] += pt * vb.z; o[7] += pt * vb.w;
            }
        }
    }

    // combine the two k-halves via smem scratch (S is free now)
    __syncthreads();
    float* scratch = S;
    if (half == 1) {
        #pragma unroll
        for (int j = 0; j < 8; j++) scratch[u * 8 + j] = o[j];
    }
    __syncthreads();
    if (half == 0) {
        float* op = gout + ((size_t)bh * NSEQ + q0 + rr) * DH + cc;
        #pragma unroll
        for (int j = 0; j < 8; j++) op[j] = o[j] + scratch[u * 8 + j];
    }
}

extern "C" void kernel_launch(void* const* d_in, const int* in_sizes, int n_in,
                              void* d_out, int out_size)
{
    const float* q    = (const float*)d_in[0];
    const float* k    = (const float*)d_in[1];
    const float* v    = (const float*)d_in[2];
    const int*   mask = (const int*)d_in[3];

    float* out  = (float*)d_out;
    float* attn = out + (size_t)2 * 16 * 2048 * 64;   // output first, then attn

    static_assert(SMEM_BYTES <= 232448, "smem over sm_103a limit");
    cudaFuncSetAttribute(attn_fused_kernel,
                         cudaFuncAttributeMaxDynamicSharedMemorySize, SMEM_BYTES);

    dim3 grid(NSEQ / TQ, 32);   // 128 q-tiles x 32 (b*h); x-fastest keeps K/V hot in L2
    attn_fused_kernel<<<grid, THREADS, SMEM_BYTES>>>(q, k, v, mask, out, attn);
}

// round 4
// speedup vs baseline: 5.8702x; 5.8702x over previous
#include <cuda_runtime.h>
#include <cuda_bf16.h>
#include <cstdint>

#define NSEQ 2048
#define DH 64
#define NBH 32
#define MTILE 64
#define CHUNK 64
#define NCHUNK (NSEQ/CHUNK)
#define NELEM (NBH*NSEQ*DH)   // 4194304

// preconverted bf16 hi/lo operands (q pre-scaled by 1/8)
__device__ __align__(16) __nv_bfloat16 g_qhi[NELEM], g_qlo[NELEM];
__device__ __align__(16) __nv_bfloat16 g_khi[NELEM], g_klo[NELEM];
__device__ __align__(16) __nv_bfloat16 g_vhi[NELEM], g_vlo[NELEM];

// smem: mask(8KB) | Qhi | Qlo | 2 x [Khi|Klo|Vhi|Vlo] tiles, 144B row stride
#define SM_MASK 0
#define SM_QHI 8192
#define SM_QLO 17408
#define SM_BUF 26624
#define TILE_B 9216
#define BUF_B  (4*TILE_B)
#define SMEM_TOTAL (SM_BUF + 2*BUF_B)   // 100352

#define CP16(d,s)   asm volatile("cp.async.cg.shared.global [%0], [%1], 16;"::"r"(d),"l"(s))
#define CP_COMMIT() asm volatile("cp.async.commit_group;")
#define CP_WAIT1()  asm volatile("cp.async.wait_group 1;")
#define LDSM4(r0,r1,r2,r3,a)  asm volatile("ldmatrix.sync.aligned.m8n8.x4.shared.b16 {%0,%1,%2,%3},[%4];":"=r"(r0),"=r"(r1),"=r"(r2),"=r"(r3):"r"(a))
#define LDSM4T(r0,r1,r2,r3,a) asm volatile("ldmatrix.sync.aligned.m8n8.x4.trans.shared.b16 {%0,%1,%2,%3},[%4];":"=r"(r0),"=r"(r1),"=r"(r2),"=r"(r3):"r"(a))

static __device__ __forceinline__ uint32_t smem_u32(const void* p){
    uint32_t a; asm("{ .reg .u64 t; cvta.to.shared.u64 t, %1; cvt.u32.u64 %0, t; }":"=r"(a):"l"(p)); return a;
}
static __device__ __forceinline__ void mma_bf16(float* d, const uint32_t* a, uint32_t b0, uint32_t b1){
    asm volatile("mma.sync.aligned.m16n8k16.row.col.f32.bf16.bf16.f32 "
        "{%0,%1,%2,%3},{%4,%5,%6,%7},{%8,%9},{%0,%1,%2,%3};"
        :"+f"(d[0]),"+f"(d[1]),"+f"(d[2]),"+f"(d[3])
        :"r"(a[0]),"r"(a[1]),"r"(a[2]),"r"(a[3]),"r"(b0),"r"(b1));
}
static __device__ __forceinline__ uint32_t packbf(float a, float b){
    __nv_bfloat162 t; t.x=__float2bfloat16(a); t.y=__float2bfloat16(b);
    return *(uint32_t*)&t;
}
// stage one 64x64 bf16 tile (rows of 128B) into smem with 144B stride
static __device__ __forceinline__ void stage1(uint32_t dst, const __nv_bfloat16* src, int kk0, int tid){
#pragma unroll
    for(int i=0;i<4;i++){
        int idx=tid+i*128, row=idx>>3, seg=idx&7;
        CP16(dst+row*144+seg*16, src+(size_t)(kk0+row)*DH+seg*8);
    }
}
static __device__ __forceinline__ void stage4(uint32_t dst, const __nv_bfloat16* k1, const __nv_bfloat16* k2,
                                              const __nv_bfloat16* v1, const __nv_bfloat16* v2, int kk0, int tid){
    stage1(dst,          k1, kk0, tid);
    stage1(dst+TILE_B,   k2, kk0, tid);
    stage1(dst+2*TILE_B, v1, kk0, tid);
    stage1(dst+3*TILE_B, v2, kk0, tid);
}

static __device__ __forceinline__ void split_store(__nv_bfloat16* hi, __nv_bfloat16* lo, int i, float4 x, float sc){
    x.x*=sc; x.y*=sc; x.z*=sc; x.w*=sc;
    __nv_bfloat16 h0=__float2bfloat16(x.x), h1=__float2bfloat16(x.y);
    __nv_bfloat16 h2=__float2bfloat16(x.z), h3=__float2bfloat16(x.w);
    __nv_bfloat16 l0=__float2bfloat16(x.x-__bfloat162float(h0));
    __nv_bfloat16 l1=__float2bfloat16(x.y-__bfloat162float(h1));
    __nv_bfloat16 l2=__float2bfloat16(x.z-__bfloat162float(h2));
    __nv_bfloat16 l3=__float2bfloat16(x.w-__bfloat162float(h3));
    __nv_bfloat162 a{h0,h1}, b{h2,h3}, c{l0,l1}, d{l2,l3};
    ((uint2*)hi)[i] = make_uint2(*(uint32_t*)&a, *(uint32_t*)&b);
    ((uint2*)lo)[i] = make_uint2(*(uint32_t*)&c, *(uint32_t*)&d);
}
__global__ void preconv_kernel(const float4* __restrict__ q, const float4* __restrict__ k, const float4* __restrict__ v){
    int i = blockIdx.x*blockDim.x + threadIdx.x;   // NELEM/4 threads
    split_store(g_qhi, g_qlo, i, q[i], 0.125f);
    split_store(g_khi, g_klo, i, k[i], 1.0f);
    split_store(g_vhi, g_vlo, i, v[i], 1.0f);
}

__global__ void __launch_bounds__(128,2)
attn_mma_kernel(const int* __restrict__ gmask, float* __restrict__ gout, float* __restrict__ gattn)
{
    extern __shared__ __align__(16) char smem[];
    const uint32_t sb = smem_u32(smem);
    const int tid=threadIdx.x, lane=tid&31, w=tid>>5;
    const int gid=lane>>2, tig=lane&3;
    const int bh=blockIdx.y, b=bh>>4, q0=blockIdx.x*MTILE;

    const __nv_bfloat16* khi_g = g_khi + (size_t)bh*NSEQ*DH;
    const __nv_bfloat16* klo_g = g_klo + (size_t)bh*NSEQ*DH;
    const __nv_bfloat16* vhi_g = g_vhi + (size_t)bh*NSEQ*DH;
    const __nv_bfloat16* vlo_g = g_vlo + (size_t)bh*NSEQ*DH;

    // group0: mask row + Q hi/lo tiles
    {
        const int* msrc = gmask + b*NSEQ;
#pragma unroll
        for(int i=0;i<4;i++){ int e4=tid+i*128; CP16(sb+SM_MASK+e4*16, msrc+e4*4); }
        const __nv_bfloat16* qh = g_qhi + ((size_t)bh*NSEQ+q0)*DH;
        const __nv_bfloat16* ql = g_qlo + ((size_t)bh*NSEQ+q0)*DH;
#pragma unroll
        for(int i=0;i<4;i++){
            int idx=tid+i*128, row=idx>>3, seg=idx&7;
            CP16(sb+SM_QHI+row*144+seg*16, qh+(size_t)row*DH+seg*8);
            CP16(sb+SM_QLO+row*144+seg*16, ql+(size_t)row*DH+seg*8);
        }
        CP_COMMIT();
    }
    // group1: Khi chunk 0
    stage1(sb+SM_BUF, khi_g, 0, tid); CP_COMMIT();
    CP_WAIT1(); __syncthreads();

    // Q A-fragments (persist in registers)
    uint32_t qhiF[4][4], qloF[4][4];
    {
        int lrow=(lane&7)+((lane>>3)&1)*8, lcol=(lane>>4)*16;
#pragma unroll
        for(int ks=0;ks<4;ks++){
            uint32_t a = sb+SM_QHI+(uint32_t)(w*16+lrow)*144+ks*32+lcol;
            LDSM4(qhiF[ks][0],qhiF[ks][1],qhiF[ks][2],qhiF[ks][3],a);
            a = sb+SM_QLO+(uint32_t)(w*16+lrow)*144+ks*32+lcol;
            LDSM4(qloF[ks][0],qloF[ks][1],qloF[ks][2],qloF[ks][3],a);
        }
    }
    const int mq0 = gmask[b*NSEQ+q0+w*16+gid];
    const int mq1 = gmask[b*NSEQ+q0+w*16+gid+8];
    const int* smask = (const int*)smem;
    const int rB=((lane>>4)&1)*8+(lane&7), cB=((lane>>3)&1)*16;   // K B-frag addressing
    const int rV=((lane>>3)&1)*8+(lane&7), cV=(lane>>4)*16;       // V B-frag (trans) addressing

    // ---------------- PASS 1: row sums ----------------
    float l0=0.f, l1=0.f;
    for(int c=0;c<NCHUNK;c++){
        if(c+1<NCHUNK) stage1(sb+SM_BUF+((c+1)&1)*BUF_B, khi_g, (c+1)*CHUNK, tid);
        CP_COMMIT(); CP_WAIT1(); __syncthreads();
        const uint32_t kb = sb+SM_BUF+(c&1)*BUF_B;
        float s[8][4];
#pragma unroll
        for(int nt=0;nt<8;nt++){ s[nt][0]=0.f;s[nt][1]=0.f;s[nt][2]=0.f;s[nt][3]=0.f; }
#pragma unroll
        for(int np=0;np<4;np++)
#pragma unroll
        for(int ks=0;ks<4;ks++){
            uint32_t b0,b1,b2,b3;
            LDSM4(b0,b1,b2,b3, kb+(uint32_t)(16*np+rB)*144+ks*32+cB);
            mma_bf16(s[2*np],   qhiF[ks], b0,b1);
            mma_bf16(s[2*np+1], qhiF[ks], b2,b3);
        }
        const int c0=c*CHUNK;
#pragma unroll
        for(int nt=0;nt<8;nt++){
            int2 mk = *(const int2*)&smask[c0+8*nt+2*tig];
            float e0 = mq0?1.f:(mk.x?0.f:__expf(s[nt][0]));
            float e1 = mq0?1.f:(mk.y?0.f:__expf(s[nt][1]));
            float e2 = mq1?1.f:(mk.x?0.f:__expf(s[nt][2]));
            float e3 = mq1?1.f:(mk.y?0.f:__expf(s[nt][3]));
            l0 += e0+e1; l1 += e2+e3;
        }
        __syncthreads();
    }
    l0 += __shfl_xor_sync(~0u,l0,1); l0 += __shfl_xor_sync(~0u,l0,2);
    l1 += __shfl_xor_sync(~0u,l1,1); l1 += __shfl_xor_sync(~0u,l1,2);
    const float inv0=1.f/l0, inv1=1.f/l1;

    // ---------------- PASS 2 ----------------
    float o[8][4];
#pragma unroll
    for(int nt=0;nt<8;nt++){ o[nt][0]=0.f;o[nt][1]=0.f;o[nt][2]=0.f;o[nt][3]=0.f; }
    float* arow0 = gattn + ((size_t)bh*NSEQ+q0+w*16+gid)*NSEQ;
    float* arow1 = arow0 + (size_t)8*NSEQ;

    stage4(sb+SM_BUF, khi_g,klo_g,vhi_g,vlo_g, 0, tid); CP_COMMIT();
    for(int c=0;c<NCHUNK;c++){
        if(c+1<NCHUNK) stage4(sb+SM_BUF+((c+1)&1)*BUF_B, khi_g,klo_g,vhi_g,vlo_g, (c+1)*CHUNK, tid);
        CP_COMMIT(); CP_WAIT1(); __syncthreads();
        const uint32_t bb = sb+SM_BUF+(c&1)*BUF_B;

        // QK 3-split
        float s[8][4];
#pragma unroll
        for(int nt=0;nt<8;nt++){ s[nt][0]=0.f;s[nt][1]=0.f;s[nt][2]=0.f;s[nt][3]=0.f; }
#pragma unroll
        for(int np=0;np<4;np++)
#pragma unroll
        for(int ks=0;ks<4;ks++){
            uint32_t h0,h1,h2,h3,e0,e1,e2,e3;
            uint32_t off = (uint32_t)(16*np+rB)*144+ks*32+cB;
            LDSM4(h0,h1,h2,h3, bb+off);
            LDSM4(e0,e1,e2,e3, bb+TILE_B+off);
            mma_bf16(s[2*np],   qhiF[ks], h0,h1); mma_bf16(s[2*np+1], qhiF[ks], h2,h3);
            mma_bf16(s[2*np],   qloF[ks], h0,h1); mma_bf16(s[2*np+1], qloF[ks], h2,h3);
            mma_bf16(s[2*np],   qhiF[ks], e0,e1); mma_bf16(s[2*np+1], qhiF[ks], e2,e3);
        }
        // epilogue: exp, normalize, attn store, repack as PV A-frags (C-layout == A-layout)
        uint32_t paH[4][4], paL[4][4];
        const int c0=c*CHUNK;
#pragma unroll
        for(int nt=0;nt<8;nt++){
            int2 mk = *(const int2*)&smask[c0+8*nt+2*tig];
            float p0 = (mq0?1.f:(mk.x?0.f:__expf(s[nt][0])))*inv0;
            float p1 = (mq0?1.f:(mk.y?0.f:__expf(s[nt][1])))*inv0;
            float p2 = (mq1?1.f:(mk.x?0.f:__expf(s[nt][2])))*inv1;
            float p3 = (mq1?1.f:(mk.y?0.f:__expf(s[nt][3])))*inv1;
            *(float2*)(arow0 + c0+8*nt+2*tig) = make_float2(p0,p1);
            *(float2*)(arow1 + c0+8*nt+2*tig) = make_float2(p2,p3);
            float h0=__bfloat162float(__float2bfloat16(p0));
            float h1=__bfloat162float(__float2bfloat16(p1));
            float h2=__bfloat162float(__float2bfloat16(p2));
            float h3=__bfloat162float(__float2bfloat16(p3));
            paH[nt>>1][(nt&1)*2+0] = packbf(h0,h1);
            paH[nt>>1][(nt&1)*2+1] = packbf(h2,h3);
            paL[nt>>1][(nt&1)*2+0] = packbf(p0-h0,p1-h1);
            paL[nt>>1][(nt&1)*2+1] = packbf(p2-h2,p3-h3);
        }
        // PV 3-split (V via ldmatrix.trans)
#pragma unroll
        for(int np=0;np<4;np++)
#pragma unroll
        for(int ks=0;ks<4;ks++){
            uint32_t h0,h1,h2,h3,g0,g1,g2,g3;
            uint32_t off = (uint32_t)(16*ks+rV)*144+np*32+cV;
            LDSM4T(h0,h1,h2,h3, bb+2*TILE_B+off);
            LDSM4T(g0,g1,g2,g3, bb+3*TILE_B+off);
            mma_bf16(o[2*np],   paH[ks], h0,h1); mma_bf16(o[2*np+1], paH[ks], h2,h3);
            mma_bf16(o[2*np],   paL[ks], h0,h1); mma_bf16(o[2*np+1], paL[ks], h2,h3);
            mma_bf16(o[2*np],   paH[ks], g0,g1); mma_bf16(o[2*np+1], paH[ks], g2,g3);
        }
        __syncthreads();
    }
    // store O
    float* orow0 = gout + ((size_t)bh*NSEQ+q0+w*16+gid)*DH;
    float* orow1 = orow0 + 8*DH;
#pragma unroll
    for(int nt=0;nt<8;nt++){
        *(float2*)(orow0 + 8*nt+2*tig) = make_float2(o[nt][0],o[nt][1]);
        *(float2*)(orow1 + 8*nt+2*tig) = make_float2(o[nt][2],o[nt][3]);
    }
}

extern "C" void kernel_launch(void* const* d_in, const int* in_sizes, int n_in,
                              void* d_out, int out_size)
{
    const float* q=(const float*)d_in[0];
    const float* k=(const float*)d_in[1];
    const float* v=(const float*)d_in[2];
    const int* mask=(const int*)d_in[3];
    float* out=(float*)d_out;
    float* attn=out + (size_t)NBH*NSEQ*DH;

    preconv_kernel<<<NELEM/4/256, 256>>>((const float4*)q,(const float4*)k,(const float4*)v);

    static_assert(SMEM_TOTAL <= 232448, "smem");
    cudaFuncSetAttribute(attn_mma_kernel, cudaFuncAttributeMaxDynamicSharedMemorySize, SMEM_TOTAL);
    attn_mma_kernel<<<dim3(NSEQ/MTILE, NBH), 128, SMEM_TOTAL>>>(mask, out, attn);
}